// round 6
// baseline (speedup 1.0000x reference)
#include <cuda_runtime.h>
#include <cuda_bf16.h>
#include <cstdint>

#define NR 2048
#define KDIM 512
#define DD 64

// allocation-free scratch
__device__ float g_z[NR * DD];
__device__ float g_zw[NR * DD];
__device__ float g_a[NR];
__device__ float g_b[NR];

// ---------------- helpers ----------------
__device__ __forceinline__ unsigned long long dup_f32(float s) {
    unsigned long long d;
    asm("mov.b64 %0, {%1, %1};" : "=l"(d) : "r"(__float_as_uint(s)));
    return d;
}
__device__ __forceinline__ void ffma2(unsigned long long &acc, unsigned long long a,
                                      unsigned long long b) {
    asm("fma.rn.f32x2 %0, %1, %2, %0;" : "+l"(acc) : "l"(a), "l"(b));
}
__device__ __forceinline__ float2 unpack2(unsigned long long v) {
    unsigned int lo, hi;
    asm("mov.b64 {%0, %1}, %2;" : "=r"(lo), "=r"(hi) : "l"(v));
    return make_float2(__uint_as_float(lo), __uint_as_float(hi));
}
__device__ __forceinline__ float tanh_fast(float x) {
    float y; asm("tanh.approx.f32 %0, %1;" : "=f"(y) : "f"(x)); return y;
}
// sigmoid(sigmoid(acc + a + b)); ha=0.5a, hb=0.5b precomputed.
// inner sigma = 0.5+0.5t, t = tanh(x/2); outer = deg-5 Taylor in t (abs err < 1e-5)
__device__ __forceinline__ float dsig(float acc, float ha, float hb) {
    float t = tanh_fast(fmaf(0.5f, acc, ha) + hb);
    float p = fmaf(3.5318e-5f, t, 2.72792e-4f);
    p = fmaf(p, t, -2.007434e-3f);
    p = fmaf(p, t, -7.194604e-3f);
    p = fmaf(p, t, 0.117501856f);
    p = fmaf(p, t, 0.622459331f);
    return p;
}

// ---------------- kernel B: z = x@W ; a, b, zw ----------------
// grid 128 x 256 threads: block = 16 rows x 64 cols, K=512
__global__ __launch_bounds__(256) void kB(const float* __restrict__ x,
                                          const float* __restrict__ W,
                                          const float* __restrict__ W2,
                                          const float* __restrict__ W3) {
    __shared__ float u_s[DD];
    __shared__ float v_s[DD];
    int tid = threadIdx.x;

    // u = W2[:64]@w3a, v = W2[64:]@w3a (redundant per block, trivial)
    if (tid < 128) {
        int k = tid & 63, half = tid >> 6;
        const float* w2r = W2 + (half * 64 + k) * 64;
        float s = 0.f;
        #pragma unroll
        for (int j = 0; j < 64; j += 4) {
            float4 a = *(const float4*)(w2r + j);
            float4 b = *(const float4*)(W3 + j);
            s += a.x * b.x + a.y * b.y + a.z * b.z + a.w * b.w;
        }
        if (half == 0) u_s[k] = s; else v_s[k] = s;
    }
    __syncthreads();

    int ty = tid >> 4, tx = tid & 15;
    int row = blockIdx.x * 16 + ty;
    const float* xr = x + row * KDIM;
    const float* wc = W + tx * 4;

    float z0 = 0.f, z1 = 0.f, z2 = 0.f, z3 = 0.f;
    #pragma unroll 4
    for (int c = 0; c < KDIM; c += 4) {
        float4 xv = *(const float4*)(xr + c);
        float4 w0 = *(const float4*)(wc + (c + 0) * DD);
        float4 w1 = *(const float4*)(wc + (c + 1) * DD);
        float4 w2v = *(const float4*)(wc + (c + 2) * DD);
        float4 w3v = *(const float4*)(wc + (c + 3) * DD);
        z0 = fmaf(xv.x, w0.x, z0); z1 = fmaf(xv.x, w0.y, z1);
        z2 = fmaf(xv.x, w0.z, z2); z3 = fmaf(xv.x, w0.w, z3);
        z0 = fmaf(xv.y, w1.x, z0); z1 = fmaf(xv.y, w1.y, z1);
        z2 = fmaf(xv.y, w1.z, z2); z3 = fmaf(xv.y, w1.w, z3);
        z0 = fmaf(xv.z, w2v.x, z0); z1 = fmaf(xv.z, w2v.y, z1);
        z2 = fmaf(xv.z, w2v.z, z2); z3 = fmaf(xv.z, w2v.w, z3);
        z0 = fmaf(xv.w, w3v.x, z0); z1 = fmaf(xv.w, w3v.y, z1);
        z2 = fmaf(xv.w, w3v.z, z2); z3 = fmaf(xv.w, w3v.w, z3);
    }

    *(float4*)(g_z + row * DD + tx * 4) = make_float4(z0, z1, z2, z3);

    float4 w3b = *(const float4*)(W3 + DD + tx * 4);
    *(float4*)(g_zw + row * DD + tx * 4) =
        make_float4(z0 * w3b.x, z1 * w3b.y, z2 * w3b.z, z3 * w3b.w);

    float r0 = fmaxf(z0, 0.f), r1 = fmaxf(z1, 0.f);
    float r2 = fmaxf(z2, 0.f), r3 = fmaxf(z3, 0.f);
    float4 uv = *(const float4*)(u_s + tx * 4);
    float4 vv = *(const float4*)(v_s + tx * 4);
    float pa = r0 * uv.x + r1 * uv.y + r2 * uv.z + r3 * uv.w;
    float pb = r0 * vv.x + r1 * vv.y + r2 * vv.z + r3 * vv.w;
    #pragma unroll
    for (int off = 8; off; off >>= 1) {
        pa += __shfl_down_sync(0xffffffffu, pa, off, 16);
        pb += __shfl_down_sync(0xffffffffu, pb, off, 16);
    }
    if (tx == 0) { g_a[row] = pa; g_b[row] = pb; }
}

// ---------------- kernel C: out = dsig(a_i + b_j + z_i . zw_j) ----------------
// grid (16,16) x 256 threads: 128x128 tile, 8x8 microtile, K-chunks of 32.
#define PAD 130  // even (LDS.64-aligned), (2k) bank spread -> conflict-free mainloop
__global__ __launch_bounds__(256, 2) void kC(float* __restrict__ out) {
    __shared__ float zs[32 * PAD];
    __shared__ float ws[32 * PAD];
    int tid = threadIdx.x;
    int tx = tid & 15, ty = tid >> 4;
    int rowBase = blockIdx.y * 128, colBase = blockIdx.x * 128;

    unsigned long long acc[8][4];
    #pragma unroll
    for (int q = 0; q < 8; q++)
        #pragma unroll
        for (int p = 0; p < 4; p++) acc[q][p] = 0ull;

    for (int kc = 0; kc < DD; kc += 32) {
        #pragma unroll
        for (int r = 0; r < 16; r++) {
            int e = r * 256 + tid;
            int i = e >> 5, k = e & 31;
            zs[k * PAD + i] = g_z[(rowBase + i) * DD + kc + k];
            ws[k * PAD + i] = g_zw[(colBase + i) * DD + kc + k];
        }
        __syncthreads();
        #pragma unroll 8
        for (int k = 0; k < 32; k++) {
            const float* zr = zs + k * PAD;
            const float* wr = ws + k * PAD;
            unsigned long long wp0 = *(const unsigned long long*)(wr + tx * 2);
            unsigned long long wp1 = *(const unsigned long long*)(wr + tx * 2 + 32);
            unsigned long long wp2 = *(const unsigned long long*)(wr + tx * 2 + 64);
            unsigned long long wp3 = *(const unsigned long long*)(wr + tx * 2 + 96);
            #pragma unroll
            for (int q = 0; q < 4; q++) {
                float2 zp = *(const float2*)(zr + ty * 2 + 32 * q);
                unsigned long long d0 = dup_f32(zp.x);
                unsigned long long d1 = dup_f32(zp.y);
                ffma2(acc[2 * q][0], d0, wp0); ffma2(acc[2 * q + 1][0], d1, wp0);
                ffma2(acc[2 * q][1], d0, wp1); ffma2(acc[2 * q + 1][1], d1, wp1);
                ffma2(acc[2 * q][2], d0, wp2); ffma2(acc[2 * q + 1][2], d1, wp2);
                ffma2(acc[2 * q][3], d0, wp3); ffma2(acc[2 * q + 1][3], d1, wp3);
            }
        }
        __syncthreads();
    }

    // epilogue: double sigmoid + store (16x8B contiguous per warp-row -> coalesced)
    float hb0[4], hb1[4];
    #pragma unroll
    for (int p = 0; p < 4; p++) {
        int j = colBase + tx * 2 + 32 * p;
        hb0[p] = 0.5f * g_b[j];
        hb1[p] = 0.5f * g_b[j + 1];
    }
    #pragma unroll
    for (int q = 0; q < 4; q++) {
        #pragma unroll
        for (int s = 0; s < 2; s++) {
            int i = rowBase + ty * 2 + 32 * q + s;
            float haI = 0.5f * g_a[i];
            float* orow = out + (long)i * NR + colBase + tx * 2;
            #pragma unroll
            for (int p = 0; p < 4; p++) {
                float2 f = unpack2(acc[2 * q + s][p]);
                float2 o;
                o.x = dsig(f.x, haI, hb0[p]);
                o.y = dsig(f.y, haI, hb1[p]);
                *(float2*)(orow + 32 * p) = o;
            }
        }
    }
}

extern "C" void kernel_launch(void* const* d_in, const int* in_sizes, int n_in,
                              void* d_out, int out_size) {
    const float* x  = (const float*)d_in[0];
    const float* W  = (const float*)d_in[1];
    const float* W2 = (const float*)d_in[2];
    const float* W3 = (const float*)d_in[3];
    float* out = (float*)d_out;
    kB<<<128, 256>>>(x, W, W2, W3);
    kC<<<dim3(16, 16), 256>>>(out);
}

// round 7
// speedup vs baseline: 1.5924x; 1.5924x over previous
#include <cuda_runtime.h>
#include <cuda_bf16.h>
#include <cstdint>

#define NR 2048
#define KDIM 512
#define DD 64

typedef unsigned long long ull;

// allocation-free scratch
__device__ float g_z[NR * DD];
__device__ float g_zw[NR * DD];
__device__ float g_a[NR];   // holds 0.5*a_i
__device__ float g_b[NR];   // holds 0.5*b_j

// ---------------- helpers ----------------
__device__ __forceinline__ ull dup_f32(float s) {
    ull d;
    asm("mov.b64 %0, {%1, %1};" : "=l"(d) : "r"(__float_as_uint(s)));
    return d;
}
__device__ __forceinline__ void ffma2(ull &acc, ull a, ull b) {
    asm("fma.rn.f32x2 %0, %1, %2, %0;" : "+l"(acc) : "l"(a), "l"(b));
}
__device__ __forceinline__ float2 unpack2(ull v) {
    unsigned int lo, hi;
    asm("mov.b64 {%0, %1}, %2;" : "=r"(lo), "=r"(hi) : "l"(v));
    return make_float2(__uint_as_float(lo), __uint_as_float(hi));
}
__device__ __forceinline__ float tanh_fast(float x) {
    float y; asm("tanh.approx.f32 %0, %1;" : "=f"(y) : "f"(x)); return y;
}
// sigmoid(sigmoid(acc + a + b)) with ha=0.5a, hb=0.5b.
// inner: sigma = 0.5+0.5t, t = tanh(x/2); outer: deg-5 Taylor in t (abs err < 1e-5)
__device__ __forceinline__ float dsig(float acc, float ha, float hb) {
    float t = tanh_fast(fmaf(0.5f, acc, ha) + hb);
    float p = fmaf(3.5318e-5f, t, 2.72792e-4f);
    p = fmaf(p, t, -2.007434e-3f);
    p = fmaf(p, t, -7.194604e-3f);
    p = fmaf(p, t, 0.117501856f);
    p = fmaf(p, t, 0.622459331f);
    return p;
}
__device__ __forceinline__ void cp16(uint32_t saddr, const void* g) {
    asm volatile("cp.async.cg.shared.global [%0], [%1], 16;" :: "r"(saddr), "l"(g));
}
__device__ __forceinline__ void cp_commit() {
    asm volatile("cp.async.commit_group;");
}
template <int N> __device__ __forceinline__ void cp_wait() {
    asm volatile("cp.async.wait_group %0;" :: "n"(N));
}

// ================ kernel B: z = x@W ; 0.5a, 0.5b, zw ================
// 128 blocks x 128 threads. Block: 16 rows x 64 cols, K=512 in 8 chunks of 64,
// double-buffered cp.async. Thread: 2 rows (ty) x 4 cols (tx), FFMA2.
#define XS_STRIDE 68
#define WS_STRIDE 68
__global__ __launch_bounds__(128) void kB(const float* __restrict__ x,
                                          const float* __restrict__ W,
                                          const float* __restrict__ W2,
                                          const float* __restrict__ W3) {
    __shared__ __align__(16) float xsB[2 * 16 * XS_STRIDE];
    __shared__ __align__(16) float wsB[2 * 64 * WS_STRIDE];
    __shared__ float u_s[DD];
    __shared__ float v_s[DD];

    const int tid = threadIdx.x;
    const int tx = tid & 15, ty = tid >> 4;
    const int rowBase = blockIdx.x * 16;

    // u = W2[:64]@w3a, v = W2[64:]@w3a  (128 threads, one row each)
    {
        int k = tid & 63, half = tid >> 6;
        const float* w2r = W2 + (half * 64 + k) * 64;
        float s = 0.f;
        #pragma unroll
        for (int j = 0; j < 64; j += 4) {
            float4 a = *(const float4*)(w2r + j);
            float4 b = *(const float4*)(W3 + j);
            s += a.x * b.x + a.y * b.y + a.z * b.z + a.w * b.w;
        }
        if (half == 0) u_s[k] = s; else v_s[k] = s;
    }

    uint32_t xs_s = (uint32_t)__cvta_generic_to_shared(xsB);
    uint32_t ws_s = (uint32_t)__cvta_generic_to_shared(wsB);

    // fill(buf, kc): xs <- x[rowBase..+16][kc..+64], ws <- W[kc..+64][0..64]
    auto fill = [&](int buf, int kc) {
        uint32_t xb = xs_s + (uint32_t)(buf * 16 * XS_STRIDE) * 4u;
        uint32_t wb = ws_s + (uint32_t)(buf * 64 * WS_STRIDE) * 4u;
        #pragma unroll
        for (int j = 0; j < 2; j++) {
            int f = tid + 128 * j;          // 256 float4 of x chunk
            int r = f >> 4, c4 = f & 15;
            cp16(xb + (uint32_t)(r * XS_STRIDE + c4 * 4) * 4u,
                 x + (rowBase + r) * KDIM + kc + c4 * 4);
        }
        #pragma unroll
        for (int j = 0; j < 8; j++) {
            int f = tid + 128 * j;          // 1024 float4 of W chunk
            int k = f >> 4, c4 = f & 15;
            cp16(wb + (uint32_t)(k * WS_STRIDE + c4 * 4) * 4u,
                 W + (kc + k) * DD + c4 * 4);
        }
        cp_commit();
    };

    fill(0, 0);

    ull a00 = 0, a01 = 0, a10 = 0, a11 = 0;  // 2 rows x {cols(0,1),(2,3)}

    for (int c = 0; c < 8; c++) {
        int buf = c & 1;
        if (c < 7) { fill(buf ^ 1, (c + 1) * 64); cp_wait<1>(); }
        else       { cp_wait<0>(); }
        __syncthreads();

        const float* xr0 = xsB + buf * 16 * XS_STRIDE + (ty * 2) * XS_STRIDE;
        const float* xr1 = xr0 + XS_STRIDE;
        const float* wb  = wsB + buf * 64 * WS_STRIDE + tx * 4;
        #pragma unroll 8
        for (int k = 0; k < 64; k++) {
            ull d0 = dup_f32(xr0[k]);
            ull d1 = dup_f32(xr1[k]);
            ulonglong2 wp = *(const ulonglong2*)(wb + k * WS_STRIDE);
            ffma2(a00, d0, wp.x); ffma2(a01, d0, wp.y);
            ffma2(a10, d1, wp.x); ffma2(a11, d1, wp.y);
        }
        __syncthreads();
    }

    // epilogue: z, zw, and per-row a/b reductions
    float4 w3b = *(const float4*)(W3 + DD + tx * 4);
    float4 uv = *(const float4*)(u_s + tx * 4);
    float4 vv = *(const float4*)(v_s + tx * 4);

    #pragma unroll
    for (int rr = 0; rr < 2; rr++) {
        float2 p0 = unpack2(rr ? a10 : a00);
        float2 p1 = unpack2(rr ? a11 : a01);
        float z0 = p0.x, z1 = p0.y, z2 = p1.x, z3 = p1.y;
        int row = rowBase + ty * 2 + rr;

        *(float4*)(g_z + row * DD + tx * 4) = make_float4(z0, z1, z2, z3);
        *(float4*)(g_zw + row * DD + tx * 4) =
            make_float4(z0 * w3b.x, z1 * w3b.y, z2 * w3b.z, z3 * w3b.w);

        float r0 = fmaxf(z0, 0.f), r1 = fmaxf(z1, 0.f);
        float r2 = fmaxf(z2, 0.f), r3 = fmaxf(z3, 0.f);
        float pa = r0 * uv.x + r1 * uv.y + r2 * uv.z + r3 * uv.w;
        float pb = r0 * vv.x + r1 * vv.y + r2 * vv.z + r3 * vv.w;
        #pragma unroll
        for (int off = 8; off; off >>= 1) {
            pa += __shfl_down_sync(0xffffffffu, pa, off, 16);
            pb += __shfl_down_sync(0xffffffffu, pb, off, 16);
        }
        if (tx == 0) { g_a[row] = 0.5f * pa; g_b[row] = 0.5f * pb; }
    }
}

// ================ kernel C: out = dsig(a_i + b_j + z_i . zw_j) ================
// grid (32,8) x 256 threads. Block tile 256 rows x 64 cols, K in 2 chunks of 32.
// Thread: 16 consecutive rows (ty*16) x 4 consecutive cols (tx*4).
// Row-pairs come directly from LDS.128 as ulonglong2 (no dup movs on z side).
#define ZPAD 260   // 260*4 = 1040 bytes: 16B-aligned rows, broadcast reads
#define WPAD 68    // 68*4 = 272 bytes: 16B-aligned, contiguous 256B reads
__global__ __launch_bounds__(256, 2) void kC(float* __restrict__ out) {
    __shared__ __align__(16) float zs[32 * ZPAD];
    __shared__ __align__(16) float ws[32 * WPAD];

    const int tid = threadIdx.x;
    const int tx = tid & 15, ty = tid >> 4;
    const int colBase = blockIdx.x * 64;
    const int rowBase = blockIdx.y * 256;

    ull acc[8][4];   // 8 row-pairs x 4 cols
    #pragma unroll
    for (int rp = 0; rp < 8; rp++)
        #pragma unroll
        for (int c = 0; c < 4; c++) acc[rp][c] = 0ull;

    for (int kc = 0; kc < DD; kc += 32) {
        // fill zs[k][i] (i = row in tile), transposed from g_z
        #pragma unroll
        for (int j = 0; j < 8; j++) {
            int f = tid + 256 * j;              // 2048 float4 = 256 rows x 8
            int i = f >> 3, k4 = f & 7;
            float4 v = *(const float4*)(g_z + (rowBase + i) * DD + kc + k4 * 4);
            zs[(k4 * 4 + 0) * ZPAD + i] = v.x;
            zs[(k4 * 4 + 1) * ZPAD + i] = v.y;
            zs[(k4 * 4 + 2) * ZPAD + i] = v.z;
            zs[(k4 * 4 + 3) * ZPAD + i] = v.w;
        }
        // fill ws[k][c], transposed from g_zw
        #pragma unroll
        for (int j = 0; j < 2; j++) {
            int f = tid + 256 * j;              // 512 float4 = 64 cols x 8
            int cc = f >> 3, k4 = f & 7;
            float4 v = *(const float4*)(g_zw + (colBase + cc) * DD + kc + k4 * 4);
            ws[(k4 * 4 + 0) * WPAD + cc] = v.x;
            ws[(k4 * 4 + 1) * WPAD + cc] = v.y;
            ws[(k4 * 4 + 2) * WPAD + cc] = v.z;
            ws[(k4 * 4 + 3) * WPAD + cc] = v.w;
        }
        __syncthreads();

        #pragma unroll 8
        for (int k = 0; k < 32; k++) {
            const float* zrow = zs + k * ZPAD + ty * 16;
            ulonglong2 za = *(const ulonglong2*)(zrow);       // row-pairs 0,1
            ulonglong2 zb = *(const ulonglong2*)(zrow + 4);   // 2,3
            ulonglong2 zc = *(const ulonglong2*)(zrow + 8);   // 4,5
            ulonglong2 zd = *(const ulonglong2*)(zrow + 12);  // 6,7
            float4 w4 = *(const float4*)(ws + k * WPAD + tx * 4);
            ull w0 = dup_f32(w4.x), w1 = dup_f32(w4.y);
            ull w2 = dup_f32(w4.z), w3 = dup_f32(w4.w);
            ffma2(acc[0][0], za.x, w0); ffma2(acc[0][1], za.x, w1);
            ffma2(acc[0][2], za.x, w2); ffma2(acc[0][3], za.x, w3);
            ffma2(acc[1][0], za.y, w0); ffma2(acc[1][1], za.y, w1);
            ffma2(acc[1][2], za.y, w2); ffma2(acc[1][3], za.y, w3);
            ffma2(acc[2][0], zb.x, w0); ffma2(acc[2][1], zb.x, w1);
            ffma2(acc[2][2], zb.x, w2); ffma2(acc[2][3], zb.x, w3);
            ffma2(acc[3][0], zb.y, w0); ffma2(acc[3][1], zb.y, w1);
            ffma2(acc[3][2], zb.y, w2); ffma2(acc[3][3], zb.y, w3);
            ffma2(acc[4][0], zc.x, w0); ffma2(acc[4][1], zc.x, w1);
            ffma2(acc[4][2], zc.x, w2); ffma2(acc[4][3], zc.x, w3);
            ffma2(acc[5][0], zc.y, w0); ffma2(acc[5][1], zc.y, w1);
            ffma2(acc[5][2], zc.y, w2); ffma2(acc[5][3], zc.y, w3);
            ffma2(acc[6][0], zd.x, w0); ffma2(acc[6][1], zd.x, w1);
            ffma2(acc[6][2], zd.x, w2); ffma2(acc[6][3], zd.x, w3);
            ffma2(acc[7][0], zd.y, w0); ffma2(acc[7][1], zd.y, w1);
            ffma2(acc[7][2], zd.y, w2); ffma2(acc[7][3], zd.y, w3);
        }
        __syncthreads();
    }

    // epilogue: double sigmoid + coalesced STG.128
    float ha[16];
    #pragma unroll
    for (int q = 0; q < 4; q++)
        *(float4*)(ha + q * 4) = *(const float4*)(g_a + rowBase + ty * 16 + q * 4);
    float4 hb = *(const float4*)(g_b + colBase + tx * 4);

    #pragma unroll
    for (int rp = 0; rp < 8; rp++) {
        float2 f0 = unpack2(acc[rp][0]);
        float2 f1 = unpack2(acc[rp][1]);
        float2 f2 = unpack2(acc[rp][2]);
        float2 f3 = unpack2(acc[rp][3]);
        int r0 = rowBase + ty * 16 + rp * 2;
        float* o0 = out + (long)r0 * NR + colBase + tx * 4;
        float* o1 = o0 + NR;
        float4 v0, v1;
        v0.x = dsig(f0.x, ha[rp * 2], hb.x);
        v0.y = dsig(f1.x, ha[rp * 2], hb.y);
        v0.z = dsig(f2.x, ha[rp * 2], hb.z);
        v0.w = dsig(f3.x, ha[rp * 2], hb.w);
        v1.x = dsig(f0.y, ha[rp * 2 + 1], hb.x);
        v1.y = dsig(f1.y, ha[rp * 2 + 1], hb.y);
        v1.z = dsig(f2.y, ha[rp * 2 + 1], hb.z);
        v1.w = dsig(f3.y, ha[rp * 2 + 1], hb.w);
        *(float4*)o0 = v0;
        *(float4*)o1 = v1;
    }
}

extern "C" void kernel_launch(void* const* d_in, const int* in_sizes, int n_in,
                              void* d_out, int out_size) {
    const float* x  = (const float*)d_in[0];
    const float* W  = (const float*)d_in[1];
    const float* W2 = (const float*)d_in[2];
    const float* W3 = (const float*)d_in[3];
    float* out = (float*)d_out;
    kB<<<128, 128>>>(x, W, W2, W3);
    kC<<<dim3(32, 8), 256>>>(out);
}

// round 11
// speedup vs baseline: 1.9764x; 1.2411x over previous
#include <cuda_runtime.h>
#include <cuda_bf16.h>
#include <cstdint>

#define NR 2048
#define KDIM 512
#define DD 64
typedef unsigned long long ull;

// allocation-free scratch (tf32-rounded GEMM operands + epilogue vectors)
__device__ __align__(128) float g_z[NR * DD];
__device__ __align__(128) float g_zw[NR * DD];
__device__ float g_a[NR];   // 0.5*a_i
__device__ float g_b[NR];   // 0.5*b_j

// ---------------- scalar helpers ----------------
__device__ __forceinline__ ull dup_f32(float s) {
    ull d; asm("mov.b64 %0, {%1, %1};" : "=l"(d) : "r"(__float_as_uint(s))); return d;
}
__device__ __forceinline__ void ffma2(ull &acc, ull a, ull b) {
    asm("fma.rn.f32x2 %0, %1, %2, %0;" : "+l"(acc) : "l"(a), "l"(b));
}
__device__ __forceinline__ float2 unpack2(ull v) {
    unsigned lo, hi; asm("mov.b64 {%0, %1}, %2;" : "=r"(lo), "=r"(hi) : "l"(v));
    return make_float2(__uint_as_float(lo), __uint_as_float(hi));
}
__device__ __forceinline__ float tanh_fast(float x) {
    float y; asm("tanh.approx.f32 %0, %1;" : "=f"(y) : "f"(x)); return y;
}
__device__ __forceinline__ float tf32r(float x) {
    unsigned r; asm("cvt.rna.tf32.f32 %0, %1;" : "=r"(r) : "f"(x));
    return __uint_as_float(r);
}
// sigmoid(sigmoid(acc + a + b)) with ha=0.5a, hb=0.5b.
// inner: sigma = 0.5+0.5t, t = tanh(x/2); outer: deg-5 Taylor in t (abs err < 1e-5)
__device__ __forceinline__ float dsig(float acc, float ha, float hb) {
    float t = tanh_fast(fmaf(0.5f, acc, ha) + hb);
    float p = fmaf(3.5318e-5f, t, 2.72792e-4f);
    p = fmaf(p, t, -2.007434e-3f);
    p = fmaf(p, t, -7.194604e-3f);
    p = fmaf(p, t, 0.117501856f);
    p = fmaf(p, t, 0.622459331f);
    return p;
}
__device__ __forceinline__ void cp16(uint32_t saddr, const void* g) {
    asm volatile("cp.async.cg.shared.global [%0], [%1], 16;" :: "r"(saddr), "l"(g));
}
__device__ __forceinline__ void cp_commit() { asm volatile("cp.async.commit_group;"); }
template <int N> __device__ __forceinline__ void cp_wait() {
    asm volatile("cp.async.wait_group %0;" :: "n"(N));
}

// warp-level tf32 MMA: D(16x8) += A(16x8) * B(8x8)
__device__ __forceinline__ void mma_tf32(float* c, float4 a, float2 b) {
    asm volatile(
        "mma.sync.aligned.m16n8k8.row.col.f32.tf32.tf32.f32 "
        "{%0,%1,%2,%3}, {%4,%5,%6,%7}, {%8,%9}, {%0,%1,%2,%3};"
        : "+f"(c[0]), "+f"(c[1]), "+f"(c[2]), "+f"(c[3])
        : "r"(__float_as_uint(a.x)), "r"(__float_as_uint(a.y)),
          "r"(__float_as_uint(a.z)), "r"(__float_as_uint(a.w)),
          "r"(__float_as_uint(b.x)), "r"(__float_as_uint(b.y)));
}

// ================ kernel B: z = x@W ; 0.5a, 0.5b, tf32(z), tf32(z*w3b) ================
// grid 128 x 256 threads. Block: 16 rows x 64 cols, K=512 in 8 double-buffered chunks.
// Thread: 1 row (ty=tid>>4) x 4 cols (tx=tid&15), FFMA2.
#define WS 68
__global__ __launch_bounds__(256) void kB(const float* __restrict__ x,
                                          const float* __restrict__ W,
                                          const float* __restrict__ W2,
                                          const float* __restrict__ W3) {
    __shared__ __align__(16) float wsB[2 * 64 * WS];
    __shared__ __align__(16) float xsB[2 * 16 * WS];
    __shared__ float u_s[DD];
    __shared__ float v_s[DD];

    const int tid = threadIdx.x;
    const int tx = tid & 15, ty = tid >> 4;
    const int rowBase = blockIdx.x * 16;

    if (tid < 128) {
        int k = tid & 63, half = tid >> 6;
        const float* w2r = W2 + (half * 64 + k) * 64;
        float s = 0.f;
        #pragma unroll
        for (int j = 0; j < 64; j += 4) {
            float4 a = *(const float4*)(w2r + j);
            float4 b = *(const float4*)(W3 + j);
            s += a.x * b.x + a.y * b.y + a.z * b.z + a.w * b.w;
        }
        if (half == 0) u_s[k] = s; else v_s[k] = s;
    }

    uint32_t ws_s = (uint32_t)__cvta_generic_to_shared(wsB);
    uint32_t xs_s = (uint32_t)__cvta_generic_to_shared(xsB);

    auto fill = [&](int buf, int kc) {
        uint32_t wb = ws_s + (uint32_t)(buf * 64 * WS) * 4u;
        uint32_t xb = xs_s + (uint32_t)(buf * 16 * WS) * 4u;
        #pragma unroll
        for (int j = 0; j < 4; j++) {                  // W chunk: 1024 float4
            int f = tid + 256 * j;
            int k = f >> 4, u = f & 15;
            cp16(wb + (uint32_t)(k * WS + u * 4) * 4u, W + (kc + k) * DD + u * 4);
        }
        {                                              // x chunk: 256 float4
            int r = tid >> 4, u = tid & 15;
            cp16(xb + (uint32_t)(r * WS + u * 4) * 4u, x + (rowBase + r) * KDIM + kc + u * 4);
        }
        cp_commit();
    };

    fill(0, 0);
    ull a01 = 0, a23 = 0;

    for (int c = 0; c < 8; c++) {
        int buf = c & 1;
        if (c < 7) { fill(buf ^ 1, (c + 1) * 64); cp_wait<1>(); }
        else       { cp_wait<0>(); }
        __syncthreads();

        const float* xr = xsB + buf * 16 * WS + ty * WS;
        const float* wb = wsB + buf * 64 * WS + tx * 4;
        #pragma unroll
        for (int k4 = 0; k4 < 64; k4 += 4) {
            float4 xv = *(const float4*)(xr + k4);
            ulonglong2 w0 = *(const ulonglong2*)(wb + (k4 + 0) * WS);
            ulonglong2 w1 = *(const ulonglong2*)(wb + (k4 + 1) * WS);
            ulonglong2 w2 = *(const ulonglong2*)(wb + (k4 + 2) * WS);
            ulonglong2 w3 = *(const ulonglong2*)(wb + (k4 + 3) * WS);
            ull d0 = dup_f32(xv.x), d1 = dup_f32(xv.y);
            ull d2 = dup_f32(xv.z), d3 = dup_f32(xv.w);
            ffma2(a01, d0, w0.x); ffma2(a23, d0, w0.y);
            ffma2(a01, d1, w1.x); ffma2(a23, d1, w1.y);
            ffma2(a01, d2, w2.x); ffma2(a23, d2, w2.y);
            ffma2(a01, d3, w3.x); ffma2(a23, d3, w3.y);
        }
        __syncthreads();
    }

    float2 p0 = unpack2(a01), p1 = unpack2(a23);
    float z0 = p0.x, z1 = p0.y, z2 = p1.x, z3 = p1.y;
    int row = rowBase + ty;

    // tf32-rounded GEMM operands
    *(float4*)(g_z + row * DD + tx * 4) =
        make_float4(tf32r(z0), tf32r(z1), tf32r(z2), tf32r(z3));
    float4 w3b = *(const float4*)(W3 + DD + tx * 4);
    *(float4*)(g_zw + row * DD + tx * 4) =
        make_float4(tf32r(z0 * w3b.x), tf32r(z1 * w3b.y),
                    tf32r(z2 * w3b.z), tf32r(z3 * w3b.w));

    // full-precision a, b path
    float r0 = fmaxf(z0, 0.f), r1 = fmaxf(z1, 0.f);
    float r2 = fmaxf(z2, 0.f), r3 = fmaxf(z3, 0.f);
    float4 uv = *(const float4*)(u_s + tx * 4);
    float4 vv = *(const float4*)(v_s + tx * 4);
    float pa = r0 * uv.x + r1 * uv.y + r2 * uv.z + r3 * uv.w;
    float pb = r0 * vv.x + r1 * vv.y + r2 * vv.z + r3 * vv.w;
    #pragma unroll
    for (int off = 8; off; off >>= 1) {
        pa += __shfl_down_sync(0xffffffffu, pa, off, 16);
        pb += __shfl_down_sync(0xffffffffu, pb, off, 16);
    }
    if (tx == 0) { g_a[row] = 0.5f * pa; g_b[row] = 0.5f * pb; }
}

// ================ kernel C: mma.sync tf32 GEMM + fused double-sigmoid ================
// grid (16,16) x 256 threads. Tile 128x128, 8 warps as 2(row) x 4(col), each warp
// 64x32 via 4x4 m16n8k8 tiles, K=64 in 2 chunks of 32 (4 k-steps each).
// SMEM staged in FRAGMENT ORDER: [tile][kstep][lane][reg] with stride-33 padding so
// mainloop fragment loads are conflict-free LDS.128 (A) / LDS.64 (B).
#define ASTR 33
__global__ __launch_bounds__(256) void kC(float* __restrict__ out) {
    __shared__ __align__(16) float sA[8 * 4 * ASTR * 4];    // 16.9 KB
    __shared__ __align__(16) float sB[16 * 4 * ASTR * 2];   // 16.9 KB

    const int tid = threadIdx.x;
    const int wid = tid >> 5, lane = tid & 31;
    const int warpRow = wid >> 2, warpCol = wid & 3;
    const int rowBase = blockIdx.y * 128, colBase = blockIdx.x * 128;
    const int tg = lane >> 2, tc = lane & 3;

    float acc[4][4][4];
    #pragma unroll
    for (int m = 0; m < 4; m++)
        #pragma unroll
        for (int n = 0; n < 4; n++)
            #pragma unroll
            for (int r = 0; r < 4; r++) acc[m][n][r] = 0.f;

    for (int kc = 0; kc < DD; kc += 32) {
        // ---- stage A (g_z rows) into fragment order ----
        // frag element: a[reg] reg = colhalf*2 + rowhalf; row = 16mt + 8*rowhalf + t/4,
        // col(k within 32) = 8ks + 4*colhalf + t%4
        #pragma unroll
        for (int j = 0; j < 4; j++) {
            int f = tid + 256 * j;                 // 1024 float4: 128 rows x 8
            int row = f >> 3, c4 = f & 7;
            float4 v = *(const float4*)(g_z + (rowBase + row) * DD + kc + c4 * 4);
            int mt = row >> 4, rw = row & 15;
            int tbase = (rw & 7) * 4, rbit = rw >> 3;
            int ks = c4 >> 1, reg = (c4 & 1) * 2 + rbit;
            float* dst = sA + (mt * 4 + ks) * (ASTR * 4);
            dst[(tbase + 0) * 4 + reg] = v.x;
            dst[(tbase + 1) * 4 + reg] = v.y;
            dst[(tbase + 2) * 4 + reg] = v.z;
            dst[(tbase + 3) * 4 + reg] = v.w;
        }
        // ---- stage B (g_zw rows = B columns) into fragment order ----
        // b[r]: k(within 32) = 8ks + 4r + t%4, n = 8nt + t/4
        #pragma unroll
        for (int j = 0; j < 4; j++) {
            int f = tid + 256 * j;                 // 1024 float4: 128 cols x 8
            int col = f >> 3, c4 = f & 7;
            float4 v = *(const float4*)(g_zw + (colBase + col) * DD + kc + c4 * 4);
            int nt = col >> 3, tbase = (col & 7) * 4;
            int ks = c4 >> 1, r = c4 & 1;
            float* dst = sB + (nt * 4 + ks) * (ASTR * 2);
            dst[(tbase + 0) * 2 + r] = v.x;
            dst[(tbase + 1) * 2 + r] = v.y;
            dst[(tbase + 2) * 2 + r] = v.z;
            dst[(tbase + 3) * 2 + r] = v.w;
        }
        __syncthreads();

        #pragma unroll
        for (int ks = 0; ks < 4; ks++) {
            float4 af[4];
            float2 bf[4];
            #pragma unroll
            for (int m = 0; m < 4; m++)
                af[m] = *(const float4*)(sA +
                        ((warpRow * 4 + m) * 4 + ks) * (ASTR * 4) + lane * 4);
            #pragma unroll
            for (int n = 0; n < 4; n++)
                bf[n] = *(const float2*)(sB +
                        ((warpCol * 4 + n) * 4 + ks) * (ASTR * 2) + lane * 2);
            #pragma unroll
            for (int m = 0; m < 4; m++)
                #pragma unroll
                for (int n = 0; n < 4; n++)
                    mma_tf32(acc[m][n], af[m], bf[n]);
        }
        __syncthreads();
    }

    // ---- epilogue: double sigmoid + st.v2 ----
    float hb0[4], hb1[4];
    #pragma unroll
    for (int n = 0; n < 4; n++) {
        int c0 = colBase + warpCol * 32 + n * 8 + tc * 2;
        hb0[n] = g_b[c0];
        hb1[n] = g_b[c0 + 1];
    }
    #pragma unroll
    for (int m = 0; m < 4; m++) {
        int r0 = rowBase + warpRow * 64 + m * 16 + tg;
        float ha0 = g_a[r0], ha1 = g_a[r0 + 8];
        float* o0 = out + (long)r0 * NR + colBase + warpCol * 32 + tc * 2;
        float* o1 = o0 + 8L * NR;
        #pragma unroll
        for (int n = 0; n < 4; n++) {
            float* a4 = acc[m][n];
            float2 v0, v1;
            v0.x = dsig(a4[0], ha0, hb0[n]);
            v0.y = dsig(a4[1], ha0, hb1[n]);
            v1.x = dsig(a4[2], ha1, hb0[n]);
            v1.y = dsig(a4[3], ha1, hb1[n]);
            *(float2*)(o0 + n * 8) = v0;
            *(float2*)(o1 + n * 8) = v1;
        }
    }
}

extern "C" void kernel_launch(void* const* d_in, const int* in_sizes, int n_in,
                              void* d_out, int out_size) {
    const float* x  = (const float*)d_in[0];
    const float* W  = (const float*)d_in[1];
    const float* W2 = (const float*)d_in[2];
    const float* W3 = (const float*)d_in[3];
    float* out = (float*)d_out;
    kB<<<128, 256>>>(x, W, W2, W3);
    kC<<<dim3(16, 16), 256>>>(out);
}

// round 12
// speedup vs baseline: 2.8291x; 1.4315x over previous
#include <cuda_runtime.h>
#include <cuda_bf16.h>
#include <cstdint>

#define NR 2048
#define KDIM 512
#define DD 64
typedef unsigned long long ull;

// allocation-free scratch (tf32-rounded GEMM operands + epilogue vectors)
__device__ __align__(128) float g_z[NR * DD];
__device__ __align__(128) float g_zw[NR * DD];
__device__ float g_a[NR];   // 0.5*a_i
__device__ float g_b[NR];   // 0.5*b_j

// ---------------- helpers ----------------
__device__ __forceinline__ float tanh_fast(float x) {
    float y; asm("tanh.approx.f32 %0, %1;" : "=f"(y) : "f"(x)); return y;
}
__device__ __forceinline__ float tf32r(float x) {
    unsigned r; asm("cvt.rna.tf32.f32 %0, %1;" : "=r"(r) : "f"(x));
    return __uint_as_float(r);
}
// sigmoid(sigmoid(acc + a + b)) with ha=0.5a, hb=0.5b.
// inner: sigma = 0.5+0.5t, t = tanh(x/2); outer: deg-5 Taylor in t (abs err < 1e-5)
__device__ __forceinline__ float dsig(float acc, float ha, float hb) {
    float t = tanh_fast(fmaf(0.5f, acc, ha) + hb);
    float p = fmaf(3.5318e-5f, t, 2.72792e-4f);
    p = fmaf(p, t, -2.007434e-3f);
    p = fmaf(p, t, -7.194604e-3f);
    p = fmaf(p, t, 0.117501856f);
    p = fmaf(p, t, 0.622459331f);
    return p;
}
__device__ __forceinline__ void cp16(uint32_t saddr, const void* g) {
    asm volatile("cp.async.cg.shared.global [%0], [%1], 16;" :: "r"(saddr), "l"(g));
}
__device__ __forceinline__ void cp_commit() { asm volatile("cp.async.commit_group;"); }
template <int N> __device__ __forceinline__ void cp_wait() {
    asm volatile("cp.async.wait_group %0;" :: "n"(N));
}

// warp-level tf32 MMA: D(16x8) += A(16x8) * B(8x8)
__device__ __forceinline__ void mma_tf32(float* c, float4 a, float2 b) {
    asm volatile(
        "mma.sync.aligned.m16n8k8.row.col.f32.tf32.tf32.f32 "
        "{%0,%1,%2,%3}, {%4,%5,%6,%7}, {%8,%9}, {%0,%1,%2,%3};"
        : "+f"(c[0]), "+f"(c[1]), "+f"(c[2]), "+f"(c[3])
        : "r"(__float_as_uint(a.x)), "r"(__float_as_uint(a.y)),
          "r"(__float_as_uint(a.z)), "r"(__float_as_uint(a.w)),
          "r"(__float_as_uint(b.x)), "r"(__float_as_uint(b.y)));
}

// ================ kernel B: z = x@W via mma.sync tf32 ================
// 128 blocks x 256 thr (8 warps). Block: 16 rows x 64 cols, K=512 in 8
// double-buffered chunks of 64. Warp wid owns cols [8wid, 8wid+8) for full K:
// one m16n8 accumulator (split even/odd kstep to break the HMMA RAW chain).
// Outputs: tf32(z)->g_z, tf32(z*w3b)->g_zw, 0.5*a->g_a, 0.5*b->g_b.
#define AST 68   // 68 mod 32 = 4 -> A-frag banks 4*tg+tc : perm of 0..31
#define BST 72   // 72 mod 32 = 8 -> B-frag banks 8*tc+tg : perm of 0..31
__global__ __launch_bounds__(256) void kB(const float* __restrict__ x,
                                          const float* __restrict__ W,
                                          const float* __restrict__ W2,
                                          const float* __restrict__ W3) {
    __shared__ __align__(16) float sA[2][16][AST];   // 8.5 KB
    __shared__ __align__(16) float sB[2][64][BST];   // 36 KB
    __shared__ float u_s[DD], v_s[DD];
    __shared__ float redA[8][16], redB[8][16];

    const int tid = threadIdx.x;
    const int wid = tid >> 5, lane = tid & 31;
    const int tg = lane >> 2, tc = lane & 3;
    const int rowBase = blockIdx.x * 16;

    uint32_t sA_u = (uint32_t)__cvta_generic_to_shared(&sA[0][0][0]);
    uint32_t sB_u = (uint32_t)__cvta_generic_to_shared(&sB[0][0][0]);

    auto fill = [&](int buf, int kc) {
        {   // A: 16 rows x 16 float4 = 256 -> 1 per thread
            int row = tid >> 4, u = tid & 15;
            cp16(sA_u + (uint32_t)((buf * 16 + row) * AST + u * 4) * 4u,
                 x + (rowBase + row) * KDIM + kc + u * 4);
        }
        #pragma unroll
        for (int j = 0; j < 4; j++) {   // B: 64 k-rows x 16 float4 = 1024 -> 4/thread
            int f = tid + 256 * j;
            int k = f >> 4, u = f & 15;
            cp16(sB_u + (uint32_t)((buf * 64 + k) * BST + u * 4) * 4u,
                 W + (kc + k) * DD + u * 4);
        }
        cp_commit();
    };

    fill(0, 0);

    // u = W2[:64]@w3a, v = W2[64:]@w3a (overlapped with first cp.async fill)
    if (tid < 128) {
        int k = tid & 63, half = tid >> 6;
        const float* w2r = W2 + (half * 64 + k) * 64;
        float s = 0.f;
        #pragma unroll
        for (int j = 0; j < 64; j += 4) {
            float4 a = *(const float4*)(w2r + j);
            float4 b = *(const float4*)(W3 + j);
            s += a.x * b.x + a.y * b.y + a.z * b.z + a.w * b.w;
        }
        if (half == 0) u_s[k] = s; else v_s[k] = s;
    }

    float accE[4] = {0.f, 0.f, 0.f, 0.f};
    float accO[4] = {0.f, 0.f, 0.f, 0.f};

    for (int c = 0; c < 8; c++) {
        int buf = c & 1;
        if (c < 7) { fill(buf ^ 1, (c + 1) * 64); cp_wait<1>(); }
        else       { cp_wait<0>(); }
        __syncthreads();

        const float (*A)[AST] = sA[buf];
        const float (*B)[BST] = sB[buf];
        #pragma unroll
        for (int ks = 0; ks < 8; ks++) {
            int k0 = ks * 8;
            float4 a = make_float4(tf32r(A[tg][k0 + tc]),
                                   tf32r(A[tg + 8][k0 + tc]),
                                   tf32r(A[tg][k0 + tc + 4]),
                                   tf32r(A[tg + 8][k0 + tc + 4]));
            float2 b = make_float2(tf32r(B[k0 + tc][wid * 8 + tg]),
                                   tf32r(B[k0 + tc + 4][wid * 8 + tg]));
            mma_tf32((ks & 1) ? accO : accE, a, b);
        }
        __syncthreads();
    }

    // C frag: c0=(tg,2tc) c1=(tg,2tc+1) c2=(tg+8,2tc) c3=(tg+8,2tc+1)
    float zA0 = accE[0] + accO[0], zA1 = accE[1] + accO[1];  // row tg
    float zB0 = accE[2] + accO[2], zB1 = accE[3] + accO[3];  // row tg+8
    int col0 = wid * 8 + tc * 2;
    int r0 = rowBase + tg, r1 = r0 + 8;

    *(float2*)(g_z + r0 * DD + col0) = make_float2(tf32r(zA0), tf32r(zA1));
    *(float2*)(g_z + r1 * DD + col0) = make_float2(tf32r(zB0), tf32r(zB1));

    float w3b0 = W3[DD + col0], w3b1 = W3[DD + col0 + 1];
    *(float2*)(g_zw + r0 * DD + col0) =
        make_float2(tf32r(zA0 * w3b0), tf32r(zA1 * w3b1));
    *(float2*)(g_zw + r1 * DD + col0) =
        make_float2(tf32r(zB0 * w3b0), tf32r(zB1 * w3b1));

    // a/b partials over this warp's 2 cols, rows tg and tg+8
    float u0 = u_s[col0], u1 = u_s[col0 + 1];
    float v0 = v_s[col0], v1 = v_s[col0 + 1];
    float rA0 = fmaxf(zA0, 0.f), rA1 = fmaxf(zA1, 0.f);
    float rB0 = fmaxf(zB0, 0.f), rB1 = fmaxf(zB1, 0.f);
    float paA = rA0 * u0 + rA1 * u1, pbA = rA0 * v0 + rA1 * v1;
    float paB = rB0 * u0 + rB1 * u1, pbB = rB0 * v0 + rB1 * v1;
    // reduce over tc (lane = tg*4 + tc)
    #pragma unroll
    for (int off = 1; off <= 2; off <<= 1) {
        paA += __shfl_down_sync(0xffffffffu, paA, off);
        pbA += __shfl_down_sync(0xffffffffu, pbA, off);
        paB += __shfl_down_sync(0xffffffffu, paB, off);
        pbB += __shfl_down_sync(0xffffffffu, pbB, off);
    }
    if (tc == 0) {
        redA[wid][tg] = paA; redA[wid][tg + 8] = paB;
        redB[wid][tg] = pbA; redB[wid][tg + 8] = pbB;
    }
    __syncthreads();
    if (tid < 32) {
        int row = tid & 15;
        float s = 0.f;
        if (tid < 16) {
            #pragma unroll
            for (int w = 0; w < 8; w++) s += redA[w][row];
            g_a[rowBase + row] = 0.5f * s;
        } else {
            #pragma unroll
            for (int w = 0; w < 8; w++) s += redB[w][row];
            g_b[rowBase + row] = 0.5f * s;
        }
    }
}

// ================ kernel C: mma.sync tf32 GEMM + fused double-sigmoid ================
// (unchanged from R11 passing version)
#define ASTR 33
__global__ __launch_bounds__(256) void kC(float* __restrict__ out) {
    __shared__ __align__(16) float sA[8 * 4 * ASTR * 4];
    __shared__ __align__(16) float sB[16 * 4 * ASTR * 2];

    const int tid = threadIdx.x;
    const int wid = tid >> 5, lane = tid & 31;
    const int warpRow = wid >> 2, warpCol = wid & 3;
    const int rowBase = blockIdx.y * 128, colBase = blockIdx.x * 128;
    const int tg = lane >> 2, tc = lane & 3;

    float acc[4][4][4];
    #pragma unroll
    for (int m = 0; m < 4; m++)
        #pragma unroll
        for (int n = 0; n < 4; n++)
            #pragma unroll
            for (int r = 0; r < 4; r++) acc[m][n][r] = 0.f;

    for (int kc = 0; kc < DD; kc += 32) {
        #pragma unroll
        for (int j = 0; j < 4; j++) {
            int f = tid + 256 * j;
            int row = f >> 3, c4 = f & 7;
            float4 v = *(const float4*)(g_z + (rowBase + row) * DD + kc + c4 * 4);
            int mt = row >> 4, rw = row & 15;
            int tbase = (rw & 7) * 4, rbit = rw >> 3;
            int ks = c4 >> 1, reg = (c4 & 1) * 2 + rbit;
            float* dst = sA + (mt * 4 + ks) * (ASTR * 4);
            dst[(tbase + 0) * 4 + reg] = v.x;
            dst[(tbase + 1) * 4 + reg] = v.y;
            dst[(tbase + 2) * 4 + reg] = v.z;
            dst[(tbase + 3) * 4 + reg] = v.w;
        }
        #pragma unroll
        for (int j = 0; j < 4; j++) {
            int f = tid + 256 * j;
            int col = f >> 3, c4 = f & 7;
            float4 v = *(const float4*)(g_zw + (colBase + col) * DD + kc + c4 * 4);
            int nt = col >> 3, tbase = (col & 7) * 4;
            int ks = c4 >> 1, r = c4 & 1;
            float* dst = sB + (nt * 4 + ks) * (ASTR * 2);
            dst[(tbase + 0) * 2 + r] = v.x;
            dst[(tbase + 1) * 2 + r] = v.y;
            dst[(tbase + 2) * 2 + r] = v.z;
            dst[(tbase + 3) * 2 + r] = v.w;
        }
        __syncthreads();

        #pragma unroll
        for (int ks = 0; ks < 4; ks++) {
            float4 af[4];
            float2 bf[4];
            #pragma unroll
            for (int m = 0; m < 4; m++)
                af[m] = *(const float4*)(sA +
                        ((warpRow * 4 + m) * 4 + ks) * (ASTR * 4) + lane * 4);
            #pragma unroll
            for (int n = 0; n < 4; n++)
                bf[n] = *(const float2*)(sB +
                        ((warpCol * 4 + n) * 4 + ks) * (ASTR * 2) + lane * 2);
            #pragma unroll
            for (int m = 0; m < 4; m++)
                #pragma unroll
                for (int n = 0; n < 4; n++)
                    mma_tf32(acc[m][n], af[m], bf[n]);
        }
        __syncthreads();
    }

    float hb0[4], hb1[4];
    #pragma unroll
    for (int n = 0; n < 4; n++) {
        int c0 = colBase + warpCol * 32 + n * 8 + tc * 2;
        hb0[n] = g_b[c0];
        hb1[n] = g_b[c0 + 1];
    }
    #pragma unroll
    for (int m = 0; m < 4; m++) {
        int r0 = rowBase + warpRow * 64 + m * 16 + tg;
        float ha0 = g_a[r0], ha1 = g_a[r0 + 8];
        float* o0 = out + (long)r0 * NR + colBase + warpCol * 32 + tc * 2;
        float* o1 = o0 + 8L * NR;
        #pragma unroll
        for (int n = 0; n < 4; n++) {
            float* a4 = acc[m][n];
            float2 v0, v1;
            v0.x = dsig(a4[0], ha0, hb0[n]);
            v0.y = dsig(a4[1], ha0, hb1[n]);
            v1.x = dsig(a4[2], ha1, hb0[n]);
            v1.y = dsig(a4[3], ha1, hb1[n]);
            *(float2*)(o0 + n * 8) = v0;
            *(float2*)(o1 + n * 8) = v1;
        }
    }
}

extern "C" void kernel_launch(void* const* d_in, const int* in_sizes, int n_in,
                              void* d_out, int out_size) {
    const float* x  = (const float*)d_in[0];
    const float* W  = (const float*)d_in[1];
    const float* W2 = (const float*)d_in[2];
    const float* W3 = (const float*)d_in[3];
    float* out = (float*)d_out;
    kB<<<128, 256>>>(x, W, W2, W3);
    kC<<<dim3(16, 16), 256>>>(out);
}

// round 14
// speedup vs baseline: 3.1727x; 1.1214x over previous
#include <cuda_runtime.h>
#include <cuda_bf16.h>
#include <cstdint>

#define NR 2048
#define KDIM 512
#define DD 64
typedef unsigned long long ull;

// allocation-free scratch: fragment-order GEMM operands for kC + epilogue vectors
// gfA[mt 0..127][ks 0..7][lane 0..31][reg 0..3] : tf32(z)       (512 KB)
// gfB[nt 0..255][ks 0..7][lane 0..31][r 0..1]   : tf32(z*w3b)   (512 KB)
__device__ __align__(128) float gfA[128 * 8 * 128];
__device__ __align__(128) float gfB[256 * 8 * 64];
__device__ float g_a[NR];   // 0.5*a_i
__device__ float g_b[NR];   // 0.5*b_j

// ---------------- helpers ----------------
__device__ __forceinline__ float tanh_fast(float x) {
    float y; asm("tanh.approx.f32 %0, %1;" : "=f"(y) : "f"(x)); return y;
}
__device__ __forceinline__ float tf32r(float x) {
    unsigned r; asm("cvt.rna.tf32.f32 %0, %1;" : "=r"(r) : "f"(x));
    return __uint_as_float(r);
}
// sigmoid(sigmoid(acc + a + b)) with ha=0.5a, hb=0.5b.
// inner: sigma = 0.5+0.5t, t = tanh(x/2); outer: deg-5 Taylor in t (abs err < 1e-5)
__device__ __forceinline__ float dsig(float acc, float ha, float hb) {
    float t = tanh_fast(fmaf(0.5f, acc, ha) + hb);
    float p = fmaf(3.5318e-5f, t, 2.72792e-4f);
    p = fmaf(p, t, -2.007434e-3f);
    p = fmaf(p, t, -7.194604e-3f);
    p = fmaf(p, t, 0.117501856f);
    p = fmaf(p, t, 0.622459331f);
    return p;
}
__device__ __forceinline__ void cp16(uint32_t saddr, const void* g) {
    asm volatile("cp.async.cg.shared.global [%0], [%1], 16;" :: "r"(saddr), "l"(g));
}
__device__ __forceinline__ void cp_commit() { asm volatile("cp.async.commit_group;"); }
template <int N> __device__ __forceinline__ void cp_wait() {
    asm volatile("cp.async.wait_group %0;" :: "n"(N));
}

// warp-level tf32 MMA: D(16x8) += A(16x8) * B(8x8)
__device__ __forceinline__ void mma_tf32(float* c, float4 a, float2 b) {
    asm volatile(
        "mma.sync.aligned.m16n8k8.row.col.f32.tf32.tf32.f32 "
        "{%0,%1,%2,%3}, {%4,%5,%6,%7}, {%8,%9}, {%0,%1,%2,%3};"
        : "+f"(c[0]), "+f"(c[1]), "+f"(c[2]), "+f"(c[3])
        : "r"(__float_as_uint(a.x)), "r"(__float_as_uint(a.y)),
          "r"(__float_as_uint(a.z)), "r"(__float_as_uint(a.w)),
          "r"(__float_as_uint(b.x)), "r"(__float_as_uint(b.y)));
}

// ================ kernel B: z = x@W via mma.sync tf32 ================
// 128 blocks x 256 thr (8 warps). Block: 16 rows x 64 cols, K=512 in 8
// double-buffered chunks of 64. Warp wid owns cols [8wid, 8wid+8) for full K.
// Outputs: frag-order tf32(z)->gfA, tf32(z*w3b)->gfB, 0.5*a->g_a, 0.5*b->g_b.
#define AST 68   // 68 mod 32 = 4 -> A-frag banks 4*tg+tc : perm of 0..31
#define BST 72   // 72 mod 32 = 8 -> B-frag banks 8*tc+tg : perm of 0..31
__global__ __launch_bounds__(256) void kB(const float* __restrict__ x,
                                          const float* __restrict__ W,
                                          const float* __restrict__ W2,
                                          const float* __restrict__ W3) {
    __shared__ __align__(16) float sA[2][16][AST];
    __shared__ __align__(16) float sB[2][64][BST];
    __shared__ float u_s[DD], v_s[DD];
    __shared__ float redA[8][16], redB[8][16];

    const int tid = threadIdx.x;
    const int wid = tid >> 5, lane = tid & 31;
    const int tg = lane >> 2, tc = lane & 3;
    const int mt = blockIdx.x;
    const int rowBase = mt * 16;

    uint32_t sA_u = (uint32_t)__cvta_generic_to_shared(&sA[0][0][0]);
    uint32_t sB_u = (uint32_t)__cvta_generic_to_shared(&sB[0][0][0]);

    auto fill = [&](int buf, int kc) {
        {   // A: 16 rows x 16 float4 = 256 -> 1 per thread
            int row = tid >> 4, u = tid & 15;
            cp16(sA_u + (uint32_t)((buf * 16 + row) * AST + u * 4) * 4u,
                 x + (rowBase + row) * KDIM + kc + u * 4);
        }
        #pragma unroll
        for (int j = 0; j < 4; j++) {   // B: 64 k-rows x 16 float4 = 1024 -> 4/thread
            int f = tid + 256 * j;
            int k = f >> 4, u = f & 15;
            cp16(sB_u + (uint32_t)((buf * 64 + k) * BST + u * 4) * 4u,
                 W + (kc + k) * DD + u * 4);
        }
        cp_commit();
    };

    fill(0, 0);

    // u = W2[:64]@w3a, v = W2[64:]@w3a (overlapped with first cp.async fill)
    if (tid < 128) {
        int k = tid & 63, half = tid >> 6;
        const float* w2r = W2 + (half * 64 + k) * 64;
        float s = 0.f;
        #pragma unroll
        for (int j = 0; j < 64; j += 4) {
            float4 a = *(const float4*)(w2r + j);
            float4 b = *(const float4*)(W3 + j);
            s += a.x * b.x + a.y * b.y + a.z * b.z + a.w * b.w;
        }
        if (half == 0) u_s[k] = s; else v_s[k] = s;
    }

    float accE[4] = {0.f, 0.f, 0.f, 0.f};
    float accO[4] = {0.f, 0.f, 0.f, 0.f};

    for (int c = 0; c < 8; c++) {
        int buf = c & 1;
        if (c < 7) { fill(buf ^ 1, (c + 1) * 64); cp_wait<1>(); }
        else       { cp_wait<0>(); }
        __syncthreads();

        const float (*A)[AST] = sA[buf];
        const float (*B)[BST] = sB[buf];
        #pragma unroll
        for (int ks = 0; ks < 8; ks++) {
            int k0 = ks * 8;
            float4 a = make_float4(tf32r(A[tg][k0 + tc]),
                                   tf32r(A[tg + 8][k0 + tc]),
                                   tf32r(A[tg][k0 + tc + 4]),
                                   tf32r(A[tg + 8][k0 + tc + 4]));
            float2 b = make_float2(tf32r(B[k0 + tc][wid * 8 + tg]),
                                   tf32r(B[k0 + tc + 4][wid * 8 + tg]));
            mma_tf32((ks & 1) ? accO : accE, a, b);
        }
        __syncthreads();
    }

    // C frag: c0=(tg,2tc) c1=(tg,2tc+1) c2=(tg+8,2tc) c3=(tg+8,2tc+1)
    float zA0 = accE[0] + accO[0], zA1 = accE[1] + accO[1];  // row tg,   cols 2tc,2tc+1
    float zB0 = accE[2] + accO[2], zB1 = accE[3] + accO[3];  // row tg+8

    // ---- frag-order A stores: element (row, k): lane'=(row&7)*4+(k&3),
    // reg = 2*((k>>2)&1) + (row>>3&1). k = 8*wid + 2tc + j. Pairs (rbit0, rbit1)
    // are reg-adjacent -> STG.64.
    {
        float zr[2][2] = {{tf32r(zA0), tf32r(zB0)}, {tf32r(zA1), tf32r(zB1)}};  // [j][rbit]
        float* baseA = gfA + (mt * 8 + wid) * 128;
        #pragma unroll
        for (int j = 0; j < 2; j++) {
            int kk = 2 * tc + j;
            int lanep = tg * 4 + (kk & 3);
            int regb = (kk >> 2) * 2;
            *(float2*)(baseA + lanep * 4 + regb) = make_float2(zr[j][0], zr[j][1]);
        }
    }
    // ---- frag-order B stores: element (rowZ, k): nt=rowZ>>3 = 2mt+rbit,
    // lane'=(rowZ&7)*4+(k&3), r=(k>>2)&1 -> elem lane'*2+r.
    {
        int col0 = wid * 8 + 2 * tc;
        float w3b0 = W3[DD + col0], w3b1 = W3[DD + col0 + 1];
        float zw[2][2] = {{tf32r(zA0 * w3b0), tf32r(zB0 * w3b0)},
                          {tf32r(zA1 * w3b1), tf32r(zB1 * w3b1)}};  // [j][rbit]
        #pragma unroll
        for (int j = 0; j < 2; j++) {
            int kk = 2 * tc + j;
            int lanep = tg * 4 + (kk & 3);
            int rB = kk >> 2;
            #pragma unroll
            for (int rbit = 0; rbit < 2; rbit++) {
                float* baseB = gfB + ((2 * mt + rbit) * 8 + wid) * 64;
                baseB[lanep * 2 + rB] = zw[j][rbit];
            }
        }
    }

    // a/b partials over this warp's 2 cols, rows tg and tg+8
    {
        int col0 = wid * 8 + 2 * tc;
        float u0 = u_s[col0], u1 = u_s[col0 + 1];
        float v0 = v_s[col0], v1 = v_s[col0 + 1];
        float rA0 = fmaxf(zA0, 0.f), rA1 = fmaxf(zA1, 0.f);
        float rB0 = fmaxf(zB0, 0.f), rB1 = fmaxf(zB1, 0.f);
        float paA = rA0 * u0 + rA1 * u1, pbA = rA0 * v0 + rA1 * v1;
        float paB = rB0 * u0 + rB1 * u1, pbB = rB0 * v0 + rB1 * v1;
        #pragma unroll
        for (int off = 1; off <= 2; off <<= 1) {
            paA += __shfl_down_sync(0xffffffffu, paA, off);
            pbA += __shfl_down_sync(0xffffffffu, pbA, off);
            paB += __shfl_down_sync(0xffffffffu, paB, off);
            pbB += __shfl_down_sync(0xffffffffu, pbB, off);
        }
        if (tc == 0) {
            redA[wid][tg] = paA; redA[wid][tg + 8] = paB;
            redB[wid][tg] = pbA; redB[wid][tg + 8] = pbB;
        }
    }
    __syncthreads();
    if (tid < 32) {
        int row = tid & 15;
        float s = 0.f;
        if (tid < 16) {
            #pragma unroll
            for (int w = 0; w < 8; w++) s += redA[w][row];
            g_a[rowBase + row] = 0.5f * s;
        } else {
            #pragma unroll
            for (int w = 0; w < 8; w++) s += redB[w][row];
            g_b[rowBase + row] = 0.5f * s;
        }
    }
}

// ================ kernel C: frag-order tf32 GEMM + fused double-sigmoid ================
// grid (16,16) x 256 thr (8 warps as 2 x 4). Tile 128x128, warp = 64x32 via 4x4
// m16n8k8 tiles, K=64 = 8 ksteps. A frags: one linear 32KB cp.async of gfA into
// SMEM, conflict-free LDS.128. B frags: coalesced LDG.64 straight from gfB (L2).
__global__ __launch_bounds__(256, 2) void kC(float* __restrict__ out) {
    __shared__ __align__(16) float sA[8192];   // 32 KB: [mt 0..7][ks 0..7][128]

    const int tid = threadIdx.x;
    const int wid = tid >> 5, lane = tid & 31;
    const int warpRow = wid >> 2, warpCol = wid & 3;
    const int rowBase = blockIdx.y * 128, colBase = blockIdx.x * 128;
    const int tg = lane >> 2, tc = lane & 3;

    uint32_t sA_u = (uint32_t)__cvta_generic_to_shared(sA);
    const float* srcA = gfA + blockIdx.y * 8192;
    #pragma unroll
    for (int j = 0; j < 8; j++) {
        int f = tid + 256 * j;
        cp16(sA_u + (uint32_t)f * 16u, srcA + f * 4);
    }
    cp_commit();
    cp_wait<0>();
    __syncthreads();

    float acc[4][4][4];
    #pragma unroll
    for (int m = 0; m < 4; m++)
        #pragma unroll
        for (int n = 0; n < 4; n++)
            #pragma unroll
            for (int r = 0; r < 4; r++) acc[m][n][r] = 0.f;

    // B frag base: nt = 16*bx + warpCol*4 + n ; each nt block = 8*64 = 512 floats
    const float* gB = gfB + (blockIdx.x * 16 + warpCol * 4) * 512 + lane * 2;

    #pragma unroll
    for (int ks = 0; ks < 8; ks++) {
        float2 bf[4];
        #pragma unroll
        for (int n = 0; n < 4; n++)
            bf[n] = *(const float2*)(gB + (n * 8 + ks) * 64);
        float4 af[4];
        #pragma unroll
        for (int m = 0; m < 4; m++)
            af[m] = *(const float4*)(sA + ((warpRow * 4 + m) * 8 + ks) * 128 + lane * 4);
        #pragma unroll
        for (int m = 0; m < 4; m++)
            #pragma unroll
            for (int n = 0; n < 4; n++)
                mma_tf32(acc[m][n], af[m], bf[n]);
    }

    // ---- epilogue: double sigmoid + st.v2 ----
    float hb0[4], hb1[4];
    #pragma unroll
    for (int n = 0; n < 4; n++) {
        int c0 = colBase + warpCol * 32 + n * 8 + tc * 2;
        hb0[n] = g_b[c0];
        hb1[n] = g_b[c0 + 1];
    }
    #pragma unroll
    for (int m = 0; m < 4; m++) {
        int r0 = rowBase + warpRow * 64 + m * 16 + tg;
        float ha0 = g_a[r0], ha1 = g_a[r0 + 8];
        float* o0 = out + (long)r0 * NR + colBase + warpCol * 32 + tc * 2;
        float* o1 = o0 + 8L * NR;
        #pragma unroll
        for (int n = 0; n < 4; n++) {
            float* a4 = acc[m][n];
            float2 v0, v1;
            v0.x = dsig(a4[0], ha0, hb0[n]);
            v0.y = dsig(a4[1], ha0, hb1[n]);
            v1.x = dsig(a4[2], ha1, hb0[n]);
            v1.y = dsig(a4[3], ha1, hb1[n]);
            *(float2*)(o0 + n * 8) = v0;
            *(float2*)(o1 + n * 8) = v1;
        }
    }
}

extern "C" void kernel_launch(void* const* d_in, const int* in_sizes, int n_in,
                              void* d_out, int out_size) {
    const float* x  = (const float*)d_in[0];
    const float* W  = (const float*)d_in[1];
    const float* W2 = (const float*)d_in[2];
    const float* W3 = (const float*)d_in[3];
    float* out = (float*)d_out;
    kB<<<128, 256>>>(x, W, W2, W3);
    kC<<<dim3(16, 16), 256>>>(out);
}